// round 1
// baseline (speedup 1.0000x reference)
#include <cuda_runtime.h>
#include <cuda_bf16.h>
#include <cuda_fp8.h>
#include <mma.h>
#include <math.h>

using namespace nvcuda;

#define NTOK   8192
#define DMODEL 2048
#define DFF    2048
#define NEXP   8
#define NASSIGN (NTOK*2)
#define MAXTILES 136

// ---------------- device scratch (no allocations allowed) ----------------
__device__ unsigned g_amax_bits;
__device__ float    g_scale_x;
__device__ int      g_count[NEXP];
__device__ int      g_cursor[NEXP];
__device__ int      g_offset[NEXP+1];
__device__ int      g_eid[NASSIGN];
__device__ float    g_cw[NASSIGN];
__device__ int      g_list[NASSIGN];
__device__ int      g_ntiles;
__device__ int      g_tile_e[MAXTILES];
__device__ int      g_tile_r[MAXTILES];

__device__ __align__(16) __nv_bfloat16 g_xq[(size_t)NTOK*DMODEL];              // 32 MB
__device__ __align__(16) __nv_bfloat16 g_w13[(size_t)NEXP*2*DFF*DMODEL];       // 134 MB
__device__ __align__(16) __nv_bfloat16 g_w2 [(size_t)NEXP*DMODEL*DFF];         // 67 MB
__device__ __align__(16) float         g_h   [(size_t)NASSIGN*DFF];            // 134 MB
__device__ __align__(16) float         g_part[(size_t)NASSIGN*DMODEL];         // 134 MB

// ---------------- small kernels ----------------
__global__ void k_zero() {
    int t = threadIdx.x;
    if (t == 0) g_amax_bits = 0u;
    if (t < NEXP) { g_count[t] = 0; g_cursor[t] = 0; }
}

__global__ void k_amax(const float4* __restrict__ x, int n4) {
    float m = 0.f;
    for (int i = blockIdx.x*blockDim.x + threadIdx.x; i < n4; i += gridDim.x*blockDim.x) {
        float4 v = x[i];
        m = fmaxf(m, fmaxf(fmaxf(fabsf(v.x), fabsf(v.y)), fmaxf(fabsf(v.z), fabsf(v.w))));
    }
    for (int o = 16; o; o >>= 1) m = fmaxf(m, __shfl_xor_sync(0xffffffffu, m, o));
    __shared__ float sm[8];
    if ((threadIdx.x & 31) == 0) sm[threadIdx.x >> 5] = m;
    __syncthreads();
    if (threadIdx.x < 8) {
        float v = sm[threadIdx.x];
        for (int o = 4; o; o >>= 1) v = fmaxf(v, __shfl_xor_sync(0xffu, v, o));
        if (threadIdx.x == 0) atomicMax(&g_amax_bits, __float_as_uint(v));
    }
}

__global__ void k_setscale() {
    float amax = __uint_as_float(g_amax_bits);
    g_scale_x = fmaxf(amax, 1e-12f) / 448.0f;
}

__global__ void k_quant(const float* __restrict__ x, int n) {
    float s = g_scale_x;
    for (int i = blockIdx.x*blockDim.x + threadIdx.x; i < n; i += gridDim.x*blockDim.x) {
        float v = x[i] / s;                 // true fp32 division to match reference
        __nv_fp8_e4m3 q(v);                 // RN, satfinite (in-range by construction)
        g_xq[i] = __float2bfloat16(float(q)); // e4m3 exact in bf16
    }
}

__global__ void k_route(const float* __restrict__ gating) {
    int t = blockIdx.x*blockDim.x + threadIdx.x;
    if (t >= NTOK) return;
    float g[NEXP];
    #pragma unroll
    for (int e = 0; e < NEXP; e++) g[e] = gating[t*NEXP + e];
    int i0 = 0; float b0 = g[0];
    #pragma unroll
    for (int e = 1; e < NEXP; e++) if (g[e] > b0) { b0 = g[e]; i0 = e; }
    int i1 = -1; float b1 = -INFINITY;
    #pragma unroll
    for (int e = 0; e < NEXP; e++) if (e != i0 && g[e] > b1) { b1 = g[e]; i1 = e; }
    float r  = expf(b1 - b0);
    float w0 = 1.f / (1.f + r);
    float w1 = r  / (1.f + r);
    g_eid[2*t]   = i0; g_cw[2*t]   = w0;
    g_eid[2*t+1] = i1; g_cw[2*t+1] = w1;
    atomicAdd(&g_count[i0], 1);
    atomicAdd(&g_count[i1], 1);
}

__global__ void k_sched() {
    if (threadIdx.x != 0 || blockIdx.x != 0) return;
    int off = 0;
    for (int e = 0; e < NEXP; e++) { g_offset[e] = off; off += g_count[e]; }
    g_offset[NEXP] = off;
    int nt = 0;
    for (int e = 0; e < NEXP; e++)
        for (int r = g_offset[e]; r < g_offset[e+1]; r += 128) {
            g_tile_e[nt] = e; g_tile_r[nt] = r; nt++;
        }
    g_ntiles = nt;
}

__global__ void k_scatter() {
    int t = blockIdx.x*blockDim.x + threadIdx.x;
    if (t >= NTOK) return;
    #pragma unroll
    for (int k = 0; k < 2; k++) {
        int a = 2*t + k;
        int e = g_eid[a];
        int pos = atomicAdd(&g_cursor[e], 1);
        g_list[g_offset[e] + pos] = a;
    }
}

__global__ void k_cvt13(const float4* __restrict__ src, int n4) {
    __nv_bfloat162* dst = reinterpret_cast<__nv_bfloat162*>(g_w13);
    for (int i = blockIdx.x*blockDim.x + threadIdx.x; i < n4; i += gridDim.x*blockDim.x) {
        float4 v = src[i];
        __nv_bfloat162 lo, hi;
        lo.x = __float2bfloat16(v.x); lo.y = __float2bfloat16(v.y);
        hi.x = __float2bfloat16(v.z); hi.y = __float2bfloat16(v.w);
        dst[2*i] = lo; dst[2*i+1] = hi;
    }
}

__global__ void k_cvt2(const float4* __restrict__ src, int n4) {
    __nv_bfloat162* dst = reinterpret_cast<__nv_bfloat162*>(g_w2);
    for (int i = blockIdx.x*blockDim.x + threadIdx.x; i < n4; i += gridDim.x*blockDim.x) {
        float4 v = src[i];
        __nv_bfloat162 lo, hi;
        lo.x = __float2bfloat16(v.x); lo.y = __float2bfloat16(v.y);
        hi.x = __float2bfloat16(v.z); hi.y = __float2bfloat16(v.w);
        dst[2*i] = lo; dst[2*i+1] = hi;
    }
}

// ---------------- GEMM1: h = silu(xq@Wg^T * s) * (xq@Wu^T * s) ----------------
// block: 128 rows (one expert tile) x 64 cols of gate (+ matching 64 up cols)
__global__ __launch_bounds__(256) void k_gemm1(const float* __restrict__ w13_scale) {
    int slot = blockIdx.y;
    if (slot >= g_ntiles) return;
    int e        = g_tile_e[slot];
    int row_base = g_tile_r[slot];
    int rows     = min(128, g_offset[e+1] - row_base);
    int cg       = blockIdx.x;   // 0..31 -> gate col group of 64

    __shared__ int s_asn[128];
    union Sm {
        struct { __nv_bfloat16 A[128*40]; __nv_bfloat16 Bg[64*40]; __nv_bfloat16 Bu[64*40]; } t;
        float C[128*72];
    };
    __shared__ Sm sm;

    int tid = threadIdx.x;
    if (tid < 128) s_asn[tid] = (tid < rows) ? g_list[row_base + tid] : -1;
    __syncthreads();

    int warp = tid >> 5;
    int wm = (warp & 3) * 32;
    int wn = (warp >> 2) * 32;

    wmma::fragment<wmma::accumulator,16,16,16,float> accg[2][2], accu[2][2];
    #pragma unroll
    for (int i = 0; i < 2; i++)
        #pragma unroll
        for (int j = 0; j < 2; j++) { wmma::fill_fragment(accg[i][j], 0.f); wmma::fill_fragment(accu[i][j], 0.f); }

    const __nv_bfloat16* Wg = g_w13 + (size_t)e*2*DFF*DMODEL + (size_t)(cg*64)*DMODEL;
    const __nv_bfloat16* Wu = Wg + (size_t)DFF*DMODEL;

    for (int k0 = 0; k0 < DMODEL; k0 += 32) {
        #pragma unroll
        for (int it = 0; it < 2; it++) {
            int idx = tid + it*256;
            int r = idx >> 2, c = (idx & 3) * 8;
            uint4 v = make_uint4(0u,0u,0u,0u);
            int a = s_asn[r];
            if (a >= 0) v = *(const uint4*)(g_xq + (size_t)(a >> 1)*DMODEL + k0 + c);
            *(uint4*)(sm.t.A + r*40 + c) = v;
        }
        {
            int r = tid >> 2, c = (tid & 3) * 8;
            *(uint4*)(sm.t.Bg + r*40 + c) = *(const uint4*)(Wg + (size_t)r*DMODEL + k0 + c);
            *(uint4*)(sm.t.Bu + r*40 + c) = *(const uint4*)(Wu + (size_t)r*DMODEL + k0 + c);
        }
        __syncthreads();
        #pragma unroll
        for (int kk = 0; kk < 32; kk += 16) {
            wmma::fragment<wmma::matrix_a,16,16,16,__nv_bfloat16,wmma::row_major> af[2];
            wmma::fragment<wmma::matrix_b,16,16,16,__nv_bfloat16,wmma::col_major> bg[2], bu[2];
            #pragma unroll
            for (int i = 0; i < 2; i++) wmma::load_matrix_sync(af[i], sm.t.A + (wm + 16*i)*40 + kk, 40);
            #pragma unroll
            for (int j = 0; j < 2; j++) {
                wmma::load_matrix_sync(bg[j], sm.t.Bg + (wn + 16*j)*40 + kk, 40);
                wmma::load_matrix_sync(bu[j], sm.t.Bu + (wn + 16*j)*40 + kk, 40);
            }
            #pragma unroll
            for (int i = 0; i < 2; i++)
                #pragma unroll
                for (int j = 0; j < 2; j++) {
                    wmma::mma_sync(accg[i][j], af[i], bg[j], accg[i][j]);
                    wmma::mma_sync(accu[i][j], af[i], bu[j], accu[i][j]);
                }
        }
        __syncthreads();
    }

    float sc = g_scale_x * w13_scale[e];
    #pragma unroll
    for (int i = 0; i < 2; i++)
        #pragma unroll
        for (int j = 0; j < 2; j++) {
            #pragma unroll
            for (int el = 0; el < accg[i][j].num_elements; el++) {
                float gv = accg[i][j].x[el] * sc;
                float uv = accu[i][j].x[el] * sc;
                accg[i][j].x[el] = (gv / (1.f + expf(-gv))) * uv;  // silu(g)*u
            }
            wmma::store_matrix_sync(&sm.C[(wm + 16*i)*72 + wn + 16*j], accg[i][j], 72, wmma::mem_row_major);
        }
    __syncthreads();

    #pragma unroll
    for (int it = 0; it < 8; it++) {
        int idx = tid + it*256;
        int r = idx >> 4, c = (idx & 15) * 4;
        int a = s_asn[r];
        if (a >= 0)
            *(float4*)(g_h + (size_t)a*DFF + cg*64 + c) = *(const float4*)(sm.C + r*72 + c);
    }
}

// ---------------- GEMM2: part = (h_hi + h_lo) @ W2^T * w2_scale ----------------
__global__ __launch_bounds__(256) void k_gemm2(const float* __restrict__ w2_scale) {
    int slot = blockIdx.y;
    if (slot >= g_ntiles) return;
    int e        = g_tile_e[slot];
    int row_base = g_tile_r[slot];
    int rows     = min(128, g_offset[e+1] - row_base);
    int cg       = blockIdx.x;   // 0..31 -> output col group of 64

    __shared__ int s_asn[128];
    union Sm {
        struct { __nv_bfloat16 Ah[128*40]; __nv_bfloat16 Al[128*40]; __nv_bfloat16 B[64*40]; } t;
        float C[128*72];
    };
    __shared__ Sm sm;

    int tid = threadIdx.x;
    if (tid < 128) s_asn[tid] = (tid < rows) ? g_list[row_base + tid] : -1;
    __syncthreads();

    int warp = tid >> 5;
    int wm = (warp & 3) * 32;
    int wn = (warp >> 2) * 32;

    wmma::fragment<wmma::accumulator,16,16,16,float> acc[2][2];
    #pragma unroll
    for (int i = 0; i < 2; i++)
        #pragma unroll
        for (int j = 0; j < 2; j++) wmma::fill_fragment(acc[i][j], 0.f);

    const __nv_bfloat16* W = g_w2 + (size_t)e*DMODEL*DFF + (size_t)(cg*64)*DFF;

    for (int k0 = 0; k0 < DFF; k0 += 32) {
        #pragma unroll
        for (int it = 0; it < 4; it++) {
            int idx = tid + it*256;
            int r = idx >> 3, c = (idx & 7) * 4;
            float4 v = make_float4(0.f,0.f,0.f,0.f);
            int a = s_asn[r];
            if (a >= 0) v = *(const float4*)(g_h + (size_t)a*DFF + k0 + c);
            float* vp = &v.x;
            #pragma unroll
            for (int j = 0; j < 4; j++) {
                float f = vp[j];
                __nv_bfloat16 h = __float2bfloat16(f);
                float lo = f - __bfloat162float(h);
                sm.t.Ah[r*40 + c + j] = h;
                sm.t.Al[r*40 + c + j] = __float2bfloat16(lo);
            }
        }
        {
            int r = tid >> 2, c = (tid & 3) * 8;
            *(uint4*)(sm.t.B + r*40 + c) = *(const uint4*)(W + (size_t)r*DFF + k0 + c);
        }
        __syncthreads();
        #pragma unroll
        for (int kk = 0; kk < 32; kk += 16) {
            wmma::fragment<wmma::matrix_a,16,16,16,__nv_bfloat16,wmma::row_major> ah[2], al[2];
            wmma::fragment<wmma::matrix_b,16,16,16,__nv_bfloat16,wmma::col_major> bf[2];
            #pragma unroll
            for (int i = 0; i < 2; i++) {
                wmma::load_matrix_sync(ah[i], sm.t.Ah + (wm + 16*i)*40 + kk, 40);
                wmma::load_matrix_sync(al[i], sm.t.Al + (wm + 16*i)*40 + kk, 40);
            }
            #pragma unroll
            for (int j = 0; j < 2; j++) wmma::load_matrix_sync(bf[j], sm.t.B + (wn + 16*j)*40 + kk, 40);
            #pragma unroll
            for (int i = 0; i < 2; i++)
                #pragma unroll
                for (int j = 0; j < 2; j++) {
                    wmma::mma_sync(acc[i][j], ah[i], bf[j], acc[i][j]);
                    wmma::mma_sync(acc[i][j], al[i], bf[j], acc[i][j]);
                }
        }
        __syncthreads();
    }

    float sc = w2_scale[e];
    #pragma unroll
    for (int i = 0; i < 2; i++)
        #pragma unroll
        for (int j = 0; j < 2; j++) {
            #pragma unroll
            for (int el = 0; el < acc[i][j].num_elements; el++) acc[i][j].x[el] *= sc;
            wmma::store_matrix_sync(&sm.C[(wm + 16*i)*72 + wn + 16*j], acc[i][j], 72, wmma::mem_row_major);
        }
    __syncthreads();

    #pragma unroll
    for (int it = 0; it < 8; it++) {
        int idx = tid + it*256;
        int r = idx >> 4, c = (idx & 15) * 4;
        int a = s_asn[r];
        if (a >= 0)
            *(float4*)(g_part + (size_t)a*DMODEL + cg*64 + c) = *(const float4*)(sm.C + r*72 + c);
    }
}

__global__ void k_combine(float* __restrict__ out) {
    const int n4 = NTOK*DMODEL/4;
    for (int i = blockIdx.x*blockDim.x + threadIdx.x; i < n4; i += gridDim.x*blockDim.x) {
        int t  = i >> 9;          // 512 float4 per row
        int c4 = i & 511;
        float w0 = g_cw[2*t], w1 = g_cw[2*t+1];
        float4 a = *((const float4*)(g_part + (size_t)(2*t  )*DMODEL) + c4);
        float4 b = *((const float4*)(g_part + (size_t)(2*t+1)*DMODEL) + c4);
        float4 o;
        o.x = w0*a.x + w1*b.x;
        o.y = w0*a.y + w1*b.y;
        o.z = w0*a.z + w1*b.z;
        o.w = w0*a.w + w1*b.w;
        ((float4*)out)[i] = o;
    }
}

// ---------------- launch ----------------
extern "C" void kernel_launch(void* const* d_in, const int* in_sizes, int n_in,
                              void* d_out, int out_size) {
    const float* x      = (const float*)d_in[0];
    const float* gating = (const float*)d_in[1];
    const float* w13q   = (const float*)d_in[2];
    const float* w13s   = (const float*)d_in[3];
    const float* w2q    = (const float*)d_in[4];
    const float* w2s    = (const float*)d_in[5];
    float* out = (float*)d_out;

    k_zero<<<1, 32>>>();
    k_amax<<<1024, 256>>>((const float4*)x, NTOK*DMODEL/4);
    k_setscale<<<1, 1>>>();
    k_quant<<<2048, 256>>>(x, NTOK*DMODEL);
    k_route<<<NTOK/256, 256>>>(gating);
    k_sched<<<1, 1>>>();
    k_scatter<<<NTOK/256, 256>>>();
    k_cvt13<<<4096, 256>>>((const float4*)w13q, NEXP*2*DFF*DMODEL/4);
    k_cvt2 <<<4096, 256>>>((const float4*)w2q,  NEXP*DMODEL*DFF/4);

    dim3 g1(32, MAXTILES);
    k_gemm1<<<g1, 256>>>(w13s);
    k_gemm2<<<g1, 256>>>(w2s);

    k_combine<<<2048, 256>>>(out);
}

// round 3
// speedup vs baseline: 1.9454x; 1.9454x over previous
#include <cuda_runtime.h>
#include <cuda_bf16.h>
#include <cuda_fp8.h>
#include <math.h>

#define NTOK   8192
#define DMODEL 2048
#define DFF    2048
#define NEXP   8
#define NASSIGN (NTOK*2)
#define MAXTILES 136
#define PADROWS 128

// ---------------- device scratch ----------------
__device__ unsigned g_amax_bits;
__device__ float    g_scale_x;
__device__ int      g_count[NEXP];
__device__ int      g_cursor[NEXP];
__device__ int      g_offset[NEXP+1];
__device__ int      g_eid[NASSIGN];
__device__ float    g_cw[NASSIGN];
__device__ int      g_list[NASSIGN];
__device__ int      g_pos[NASSIGN];
__device__ int      g_ntiles;
__device__ int      g_tile_e[MAXTILES];
__device__ int      g_tile_r[MAXTILES];

__device__ __align__(16) __nv_bfloat16 g_xq [(size_t)NTOK*DMODEL];                    // 32 MB
__device__ __align__(16) __nv_bfloat16 g_w13[(size_t)NEXP*2*DFF*DMODEL];              // 134 MB
__device__ __align__(16) __nv_bfloat16 g_w2 [(size_t)NEXP*DMODEL*DFF];                // 67 MB
__device__ __align__(16) __nv_bfloat16 g_hhi[(size_t)(NASSIGN+PADROWS)*DFF];          // 33 MB
__device__ __align__(16) __nv_bfloat16 g_hlo[(size_t)(NASSIGN+PADROWS)*DFF];          // 33 MB
__device__ __align__(16) float         g_part[(size_t)(NASSIGN+PADROWS)*DMODEL];      // 135 MB

// ---------------- PTX helpers (baseline PTX only; no 'a' features) ----------------
__device__ __forceinline__ unsigned smem_u32(const void* p) {
    return (unsigned)__cvta_generic_to_shared(p);
}
__device__ __forceinline__ void cpasync16(unsigned dst, const void* src) {
    asm volatile("cp.async.cg.shared.global [%0], [%1], 16;"::"r"(dst),"l"(src):"memory");
}
__device__ __forceinline__ void cpasync16z(unsigned dst, const void* src, int sz) {
    asm volatile("cp.async.cg.shared.global [%0], [%1], 16, %2;"::"r"(dst),"l"(src),"r"(sz):"memory");
}
#define CP_COMMIT() asm volatile("cp.async.commit_group;":::"memory")
#define CP_WAIT1()  asm volatile("cp.async.wait_group 1;":::"memory")
#define CP_WAIT0()  asm volatile("cp.async.wait_group 0;":::"memory")

__device__ __forceinline__ void ldsm4(unsigned& r0, unsigned& r1, unsigned& r2, unsigned& r3,
                                      unsigned addr) {
    asm volatile("ldmatrix.sync.aligned.m8n8.x4.shared.b16 {%0,%1,%2,%3}, [%4];"
                 : "=r"(r0), "=r"(r1), "=r"(r2), "=r"(r3) : "r"(addr));
}
__device__ __forceinline__ void mma16816(float* d, const unsigned* a, unsigned b0, unsigned b1) {
    asm volatile(
        "mma.sync.aligned.m16n8k16.row.col.f32.bf16.bf16.f32 "
        "{%0,%1,%2,%3}, {%4,%5,%6,%7}, {%8,%9}, {%0,%1,%2,%3};"
        : "+f"(d[0]), "+f"(d[1]), "+f"(d[2]), "+f"(d[3])
        : "r"(a[0]), "r"(a[1]), "r"(a[2]), "r"(a[3]), "r"(b0), "r"(b1));
}
__device__ __forceinline__ unsigned sw128(unsigned off) { return off ^ ((off >> 3) & 0x70); }

// ldmatrix address inside a SW128 K-major tile: row r (128B rows), 16B-chunk varies with kk/half
__device__ __forceinline__ unsigned ldsm_addr(unsigned tile_base, int row, int half, int kk) {
    unsigned within = (unsigned)(half*16 + kk*32);
    return tile_base + (unsigned)row*128u + (within ^ (((unsigned)row & 7u) << 4));
}

// ---------------- small kernels ----------------
__global__ void k_zero() {
    int t = threadIdx.x;
    if (t == 0) g_amax_bits = 0u;
    if (t < NEXP) { g_count[t] = 0; g_cursor[t] = 0; }
}

__global__ void k_amax(const float4* __restrict__ x, int n4) {
    float m = 0.f;
    for (int i = blockIdx.x*blockDim.x + threadIdx.x; i < n4; i += gridDim.x*blockDim.x) {
        float4 v = x[i];
        m = fmaxf(m, fmaxf(fmaxf(fabsf(v.x), fabsf(v.y)), fmaxf(fabsf(v.z), fabsf(v.w))));
    }
    for (int o = 16; o; o >>= 1) m = fmaxf(m, __shfl_xor_sync(0xffffffffu, m, o));
    __shared__ float sm[8];
    if ((threadIdx.x & 31) == 0) sm[threadIdx.x >> 5] = m;
    __syncthreads();
    if (threadIdx.x < 8) {
        float v = sm[threadIdx.x];
        for (int o = 4; o; o >>= 1) v = fmaxf(v, __shfl_xor_sync(0xffu, v, o));
        if (threadIdx.x == 0) atomicMax(&g_amax_bits, __float_as_uint(v));
    }
}

__global__ void k_setscale() {
    float amax = __uint_as_float(g_amax_bits);
    g_scale_x = fmaxf(amax, 1e-12f) / 448.0f;
}

__global__ void k_quant(const float* __restrict__ x, int n) {
    float s = g_scale_x;
    for (int i = blockIdx.x*blockDim.x + threadIdx.x; i < n; i += gridDim.x*blockDim.x) {
        float v = x[i] / s;
        __nv_fp8_e4m3 q(v);
        g_xq[i] = __float2bfloat16(float(q));
    }
}

__global__ void k_route(const float* __restrict__ gating) {
    int t = blockIdx.x*blockDim.x + threadIdx.x;
    if (t >= NTOK) return;
    float g[NEXP];
    #pragma unroll
    for (int e = 0; e < NEXP; e++) g[e] = gating[t*NEXP + e];
    int i0 = 0; float b0 = g[0];
    #pragma unroll
    for (int e = 1; e < NEXP; e++) if (g[e] > b0) { b0 = g[e]; i0 = e; }
    int i1 = -1; float b1 = -INFINITY;
    #pragma unroll
    for (int e = 0; e < NEXP; e++) if (e != i0 && g[e] > b1) { b1 = g[e]; i1 = e; }
    float r  = expf(b1 - b0);
    float w0 = 1.f / (1.f + r);
    float w1 = r  / (1.f + r);
    g_eid[2*t]   = i0; g_cw[2*t]   = w0;
    g_eid[2*t+1] = i1; g_cw[2*t+1] = w1;
    atomicAdd(&g_count[i0], 1);
    atomicAdd(&g_count[i1], 1);
}

__global__ void k_sched() {
    if (threadIdx.x != 0 || blockIdx.x != 0) return;
    int off = 0;
    for (int e = 0; e < NEXP; e++) { g_offset[e] = off; off += g_count[e]; }
    g_offset[NEXP] = off;
    int nt = 0;
    for (int e = 0; e < NEXP; e++)
        for (int r = g_offset[e]; r < g_offset[e+1]; r += 128) {
            g_tile_e[nt] = e; g_tile_r[nt] = r; nt++;
        }
    g_ntiles = nt;
}

__global__ void k_scatter() {
    int t = blockIdx.x*blockDim.x + threadIdx.x;
    if (t >= NTOK) return;
    #pragma unroll
    for (int k = 0; k < 2; k++) {
        int a = 2*t + k;
        int e = g_eid[a];
        int pos = atomicAdd(&g_cursor[e], 1);
        int p = g_offset[e] + pos;
        g_list[p] = a;
        g_pos[a] = p;
    }
}

__global__ void k_cvt(const float4* __restrict__ src, __nv_bfloat16* __restrict__ dstb, int n4) {
    __nv_bfloat162* dst = reinterpret_cast<__nv_bfloat162*>(dstb);
    for (int i = blockIdx.x*blockDim.x + threadIdx.x; i < n4; i += gridDim.x*blockDim.x) {
        float4 v = src[i];
        __nv_bfloat162 lo, hi;
        lo.x = __float2bfloat16(v.x); lo.y = __float2bfloat16(v.y);
        hi.x = __float2bfloat16(v.z); hi.y = __float2bfloat16(v.w);
        dst[2*i] = lo; dst[2*i+1] = hi;
    }
}

// ================= GEMM1 =================
// Block: M=128 rows (expert tile) x 128 gate cols + 128 up cols. 512 threads (16 warps, 4m x 4n).
// K staged 64 at a time, 3-stage cp.async pipeline, SW128 smem.
// Stage layout: A[128x128B] @ 0, B[256x128B] @ 16K (rows 0-127 gate, 128-255 up). Stage span 48KB.
#define G1_STG  49152
#define G1_BOFF 16384
#define G1_SMEM (3*G1_STG)      // 144 KB

__device__ __forceinline__ void g1_fill(unsigned sbase, const int* s_tok, const __nv_bfloat16* wb,
                                        int cg, int kc, int buf, int tid) {
    int k0 = kc * 64;
    unsigned st = sbase + (unsigned)buf * G1_STG;
    #pragma unroll
    for (int i = 0; i < 2; i++) {                 // A: 128 rows x 8 chunks
        int idx = tid + i*512;
        int r = idx >> 3, c = idx & 7;
        int tok = s_tok[r];
        unsigned dst = st + sw128((unsigned)(r*128 + c*16));
        const void* src = g_xq + ((size_t)(tok < 0 ? 0 : tok) * DMODEL + k0 + c*8);
        cpasync16z(dst, src, tok < 0 ? 0 : 16);
    }
    #pragma unroll
    for (int i = 0; i < 4; i++) {                 // B: 256 rows x 8 chunks
        int idx = tid + i*512;
        int r = idx >> 3, c = idx & 7;
        int wrow = cg*128 + (r & 127) + ((r >> 7) ? DFF : 0);
        unsigned dst = st + G1_BOFF + sw128((unsigned)(r*128 + c*16));
        cpasync16(dst, wb + (size_t)wrow*DMODEL + k0 + c*8);
    }
}

__global__ __launch_bounds__(512,1) void k_gemm1(const float* __restrict__ w13_scale) {
    int slot = blockIdx.y;
    if (slot >= g_ntiles) return;
    int cg = blockIdx.x;                               // 0..15 -> 128 gate cols
    int e = g_tile_e[slot], row_base = g_tile_r[slot];
    int rows = min(128, g_offset[e+1] - row_base);

    extern __shared__ char smc[];
    __shared__ int s_tok[128];
    unsigned sbase = smem_u32(smc);
    int tid  = threadIdx.x;
    int wid  = tid >> 5, lane = tid & 31;
    int m0   = (wid & 3) * 32;
    int n0   = (wid >> 2) * 32;                        // within 128-col gate group
    const __nv_bfloat16* wb = g_w13 + (size_t)e * 2*DFF*DMODEL;

    if (tid < 128) s_tok[tid] = (tid < rows) ? (g_list[row_base + tid] >> 1) : -1;
    __syncthreads();

    g1_fill(sbase, s_tok, wb, cg, 0, 0, tid); CP_COMMIT();
    g1_fill(sbase, s_tok, wb, cg, 1, 1, tid); CP_COMMIT();

    float acc[2][8][4];                                 // [mi][n8: 0-3 gate, 4-7 up][4]
    #pragma unroll
    for (int a = 0; a < 2; a++)
        #pragma unroll
        for (int b = 0; b < 8; b++)
            #pragma unroll
            for (int c = 0; c < 4; c++) acc[a][b][c] = 0.f;

    int arow = lane & 15, ahalf = lane >> 4;
    const int NT = DMODEL / 64;                         // 32
    for (int kt = 0; kt < NT; kt++) {
        if (kt + 2 < NT) { CP_WAIT1(); } else { CP_WAIT0(); }
        __syncthreads();
        if (kt + 2 < NT) { g1_fill(sbase, s_tok, wb, cg, kt+2, (kt+2)%3, tid); CP_COMMIT(); }

        unsigned st = sbase + (unsigned)(kt % 3) * G1_STG;
        #pragma unroll
        for (int kk = 0; kk < 4; kk++) {
            unsigned af[2][4];
            #pragma unroll
            for (int mi = 0; mi < 2; mi++)
                ldsm4(af[mi][0], af[mi][1], af[mi][2], af[mi][3],
                      ldsm_addr(st, m0 + mi*16 + arow, ahalf, kk));
            #pragma unroll
            for (int side = 0; side < 2; side++) {      // 0=gate rows, 1=up rows(+128)
                #pragma unroll
                for (int nf = 0; nf < 2; nf++) {
                    unsigned b0, b1, b2, b3;
                    int brow = side*128 + n0 + nf*16 + arow;
                    ldsm4(b0, b1, b2, b3, ldsm_addr(st + G1_BOFF, brow, ahalf, kk));
                    #pragma unroll
                    for (int mi = 0; mi < 2; mi++) {
                        mma16816(acc[mi][side*4 + nf*2 + 0], af[mi], b0, b2);
                        mma16816(acc[mi][side*4 + nf*2 + 1], af[mi], b1, b3);
                    }
                }
            }
        }
    }

    // epilogue: silu(gate)*up -> hi/lo bf16 split, store by sorted position
    float sc = g_scale_x * __ldg(w13_scale + e);
    int qrow = lane >> 2, qc2 = (lane & 3) * 2;
    #pragma unroll
    for (int mi = 0; mi < 2; mi++)
        #pragma unroll
        for (int half = 0; half < 2; half++) {
            int r = m0 + mi*16 + half*8 + qrow;
            if (r < rows) {
                size_t base = (size_t)(row_base + r) * DFF + (size_t)cg*128 + n0;
                #pragma unroll
                for (int nf = 0; nf < 4; nf++) {
                    int ei = half*2;
                    float g0 = acc[mi][nf][ei]     * sc;
                    float g1 = acc[mi][nf][ei+1]   * sc;
                    float u0 = acc[mi][4+nf][ei]   * sc;
                    float u1 = acc[mi][4+nf][ei+1] * sc;
                    float h0 = (g0 / (1.f + expf(-g0))) * u0;
                    float h1 = (g1 / (1.f + expf(-g1))) * u1;
                    __nv_bfloat16 a0 = __float2bfloat16(h0), a1 = __float2bfloat16(h1);
                    float l0 = h0 - __bfloat162float(a0);
                    float l1 = h1 - __bfloat162float(a1);
                    __nv_bfloat16 c0 = __float2bfloat16(l0), c1 = __float2bfloat16(l1);
                    unsigned hp = (unsigned)*(unsigned short*)&a0 | ((unsigned)*(unsigned short*)&a1 << 16);
                    unsigned lp = (unsigned)*(unsigned short*)&c0 | ((unsigned)*(unsigned short*)&c1 << 16);
                    size_t off = base + nf*8 + qc2;
                    *(unsigned*)(g_hhi + off) = hp;
                    *(unsigned*)(g_hlo + off) = lp;
                }
            }
        }
}

// ================= GEMM2 =================
// Block: M=128 x N=256 out cols. A = h_hi and h_lo double-accumulated. 512 threads (4m x 4n),
// warp tile 32m x 64n. Stage: Ahi@0 (16K), Alo@16K, B[256x128B]@32K. Stage span 64KB.
#define G2_STG   65536
#define G2_ALOFF 16384
#define G2_BOFF  32768
#define G2_SMEM  (3*G2_STG)     // 192 KB

__device__ __forceinline__ void g2_fill(unsigned sbase, int row_base, const __nv_bfloat16* wb,
                                        int cgo, int kc, int buf, int tid) {
    int k0 = kc * 64;
    unsigned st = sbase + (unsigned)buf * G2_STG;
    #pragma unroll
    for (int i = 0; i < 2; i++) {
        int idx = tid + i*512;
        int r = idx >> 3, c = idx & 7;
        unsigned swo = sw128((unsigned)(r*128 + c*16));
        size_t off = (size_t)(row_base + r) * DFF + k0 + c*8;
        cpasync16(st + swo,            g_hhi + off);
        cpasync16(st + G2_ALOFF + swo, g_hlo + off);
    }
    #pragma unroll
    for (int i = 0; i < 4; i++) {
        int idx = tid + i*512;
        int r = idx >> 3, c = idx & 7;
        int n = cgo*256 + r;
        unsigned dst = st + G2_BOFF + sw128((unsigned)(r*128 + c*16));
        cpasync16(dst, wb + (size_t)n*DFF + k0 + c*8);
    }
}

__global__ __launch_bounds__(512,1) void k_gemm2(const float* __restrict__ w2_scale) {
    int slot = blockIdx.y;
    if (slot >= g_ntiles) return;
    int cgo = blockIdx.x;                              // 0..7 -> 256 out cols
    int e = g_tile_e[slot], row_base = g_tile_r[slot];
    int rows = min(128, g_offset[e+1] - row_base);

    extern __shared__ char smc[];
    unsigned sbase = smem_u32(smc);
    int tid  = threadIdx.x;
    int wid  = tid >> 5, lane = tid & 31;
    int m0   = (wid & 3) * 32;
    int n0   = (wid >> 2) * 64;
    const __nv_bfloat16* wb = g_w2 + (size_t)e * DMODEL * DFF;

    g2_fill(sbase, row_base, wb, cgo, 0, 0, tid); CP_COMMIT();
    g2_fill(sbase, row_base, wb, cgo, 1, 1, tid); CP_COMMIT();

    float acc[2][8][4];
    #pragma unroll
    for (int a = 0; a < 2; a++)
        #pragma unroll
        for (int b = 0; b < 8; b++)
            #pragma unroll
            for (int c = 0; c < 4; c++) acc[a][b][c] = 0.f;

    int arow = lane & 15, ahalf = lane >> 4;
    const int NT = DFF / 64;
    for (int kt = 0; kt < NT; kt++) {
        if (kt + 2 < NT) { CP_WAIT1(); } else { CP_WAIT0(); }
        __syncthreads();
        if (kt + 2 < NT) { g2_fill(sbase, row_base, wb, cgo, kt+2, (kt+2)%3, tid); CP_COMMIT(); }

        unsigned st = sbase + (unsigned)(kt % 3) * G2_STG;
        #pragma unroll
        for (int kk = 0; kk < 4; kk++) {
            unsigned ah[2][4], al[2][4];
            #pragma unroll
            for (int mi = 0; mi < 2; mi++) {
                ldsm4(ah[mi][0], ah[mi][1], ah[mi][2], ah[mi][3],
                      ldsm_addr(st,            m0 + mi*16 + arow, ahalf, kk));
                ldsm4(al[mi][0], al[mi][1], al[mi][2], al[mi][3],
                      ldsm_addr(st + G2_ALOFF, m0 + mi*16 + arow, ahalf, kk));
            }
            #pragma unroll
            for (int nf = 0; nf < 4; nf++) {
                unsigned b0, b1, b2, b3;
                int brow = n0 + nf*16 + arow;
                ldsm4(b0, b1, b2, b3, ldsm_addr(st + G2_BOFF, brow, ahalf, kk));
                #pragma unroll
                for (int mi = 0; mi < 2; mi++) {
                    mma16816(acc[mi][nf*2 + 0], ah[mi], b0, b2);
                    mma16816(acc[mi][nf*2 + 0], al[mi], b0, b2);
                    mma16816(acc[mi][nf*2 + 1], ah[mi], b1, b3);
                    mma16816(acc[mi][nf*2 + 1], al[mi], b1, b3);
                }
            }
        }
    }

    float sc = __ldg(w2_scale + e);
    int qrow = lane >> 2, qc2 = (lane & 3) * 2;
    #pragma unroll
    for (int mi = 0; mi < 2; mi++)
        #pragma unroll
        for (int half = 0; half < 2; half++) {
            int r = m0 + mi*16 + half*8 + qrow;
            if (r < rows) {
                float* base = g_part + (size_t)(row_base + r) * DMODEL + (size_t)cgo*256 + n0;
                #pragma unroll
                for (int nf = 0; nf < 8; nf++) {
                    int ei = half*2;
                    float2 v;
                    v.x = acc[mi][nf][ei]   * sc;
                    v.y = acc[mi][nf][ei+1] * sc;
                    *(float2*)(base + nf*8 + qc2) = v;
                }
            }
        }
}

__global__ void k_combine(float* __restrict__ out) {
    const int n4 = NTOK*DMODEL/4;
    const float4* part4 = (const float4*)g_part;
    for (int i = blockIdx.x*blockDim.x + threadIdx.x; i < n4; i += gridDim.x*blockDim.x) {
        int t  = i >> 9;
        int c4 = i & 511;
        float w0 = g_cw[2*t], w1 = g_cw[2*t+1];
        int p0 = g_pos[2*t], p1 = g_pos[2*t+1];
        float4 a = part4[(size_t)p0*512 + c4];
        float4 b = part4[(size_t)p1*512 + c4];
        float4 o;
        o.x = w0*a.x + w1*b.x;
        o.y = w0*a.y + w1*b.y;
        o.z = w0*a.z + w1*b.z;
        o.w = w0*a.w + w1*b.w;
        ((float4*)out)[i] = o;
    }
}

// ---------------- launch ----------------
extern "C" void kernel_launch(void* const* d_in, const int* in_sizes, int n_in,
                              void* d_out, int out_size) {
    const float* x      = (const float*)d_in[0];
    const float* gating = (const float*)d_in[1];
    const float* w13q   = (const float*)d_in[2];
    const float* w13s   = (const float*)d_in[3];
    const float* w2q    = (const float*)d_in[4];
    const float* w2s    = (const float*)d_in[5];
    float* out = (float*)d_out;

    cudaFuncSetAttribute(k_gemm1, cudaFuncAttributeMaxDynamicSharedMemorySize, G1_SMEM);
    cudaFuncSetAttribute(k_gemm2, cudaFuncAttributeMaxDynamicSharedMemorySize, G2_SMEM);

    __nv_bfloat16* w13d; cudaGetSymbolAddress((void**)&w13d, g_w13);
    __nv_bfloat16* w2d;  cudaGetSymbolAddress((void**)&w2d,  g_w2);

    k_zero<<<1, 32>>>();
    k_amax<<<1024, 256>>>((const float4*)x, NTOK*DMODEL/4);
    k_setscale<<<1, 1>>>();
    k_quant<<<2048, 256>>>(x, NTOK*DMODEL);
    k_route<<<NTOK/256, 256>>>(gating);
    k_sched<<<1, 1>>>();
    k_scatter<<<NTOK/256, 256>>>();
    k_cvt<<<4096, 256>>>((const float4*)w13q, w13d, NEXP*2*DFF*DMODEL/4);
    k_cvt<<<4096, 256>>>((const float4*)w2q,  w2d,  NEXP*DMODEL*DFF/4);

    dim3 gg1(16, MAXTILES);
    k_gemm1<<<gg1, 512, G1_SMEM>>>(w13s);
    dim3 gg2(8, MAXTILES);
    k_gemm2<<<gg2, 512, G2_SMEM>>>(w2s);

    k_combine<<<2048, 256>>>(out);
}

// round 4
// speedup vs baseline: 1.9718x; 1.0136x over previous
#include <cuda_runtime.h>
#include <cuda_bf16.h>
#include <cuda_fp8.h>
#include <math.h>

#define NTOK   8192
#define DMODEL 2048
#define DFF    2048
#define NEXP   8
#define NASSIGN (NTOK*2)
#define MAXTILES 136
#define PADROWS 128

// ---------------- device scratch ----------------
__device__ unsigned g_amax_bits;
__device__ float    g_scale_x;
__device__ float    g_inv_x;
__device__ int      g_count[NEXP];
__device__ int      g_cursor[NEXP];
__device__ int      g_offset[NEXP+1];
__device__ int      g_eid[NASSIGN];
__device__ float    g_cw[NASSIGN];
__device__ int      g_list[NASSIGN];
__device__ int      g_pos[NASSIGN];
__device__ int      g_ntiles;
__device__ int      g_tile_e[MAXTILES];
__device__ int      g_tile_r[MAXTILES];

__device__ __align__(16) __nv_bfloat16 g_xq [(size_t)NTOK*DMODEL];
__device__ __align__(16) __nv_bfloat16 g_w13[(size_t)NEXP*2*DFF*DMODEL];
__device__ __align__(16) __nv_bfloat16 g_w2 [(size_t)NEXP*DMODEL*DFF];
__device__ __align__(16) __nv_bfloat16 g_hhi[(size_t)(NASSIGN+PADROWS)*DFF];
__device__ __align__(16) __nv_bfloat16 g_hlo[(size_t)(NASSIGN+PADROWS)*DFF];
__device__ __align__(16) float         g_part[(size_t)(NASSIGN+PADROWS)*DMODEL];

// ---------------- PTX helpers ----------------
__device__ __forceinline__ unsigned smem_u32(const void* p) {
    return (unsigned)__cvta_generic_to_shared(p);
}
__device__ __forceinline__ void cpasync16(unsigned dst, const void* src) {
    asm volatile("cp.async.cg.shared.global [%0], [%1], 16;"::"r"(dst),"l"(src):"memory");
}
__device__ __forceinline__ void cpasync16z(unsigned dst, const void* src, int sz) {
    asm volatile("cp.async.cg.shared.global [%0], [%1], 16, %2;"::"r"(dst),"l"(src),"r"(sz):"memory");
}
#define CP_COMMIT() asm volatile("cp.async.commit_group;":::"memory")
#define CP_WAIT1()  asm volatile("cp.async.wait_group 1;":::"memory")
#define CP_WAIT0()  asm volatile("cp.async.wait_group 0;":::"memory")

__device__ __forceinline__ void ldsm4(unsigned& r0, unsigned& r1, unsigned& r2, unsigned& r3,
                                      unsigned addr) {
    asm volatile("ldmatrix.sync.aligned.m8n8.x4.shared.b16 {%0,%1,%2,%3}, [%4];"
                 : "=r"(r0), "=r"(r1), "=r"(r2), "=r"(r3) : "r"(addr));
}
__device__ __forceinline__ void mma16816(float* d, const unsigned* a, unsigned b0, unsigned b1) {
    asm volatile(
        "mma.sync.aligned.m16n8k16.row.col.f32.bf16.bf16.f32 "
        "{%0,%1,%2,%3}, {%4,%5,%6,%7}, {%8,%9}, {%0,%1,%2,%3};"
        : "+f"(d[0]), "+f"(d[1]), "+f"(d[2]), "+f"(d[3])
        : "r"(a[0]), "r"(a[1]), "r"(a[2]), "r"(a[3]), "r"(b0), "r"(b1));
}
__device__ __forceinline__ unsigned sw128(unsigned off) { return off ^ ((off >> 3) & 0x70); }
__device__ __forceinline__ unsigned ldsm_addr(unsigned tile_base, int row, int half, int kk) {
    unsigned within = (unsigned)(half*16 + kk*32);
    return tile_base + (unsigned)row*128u + (within ^ (((unsigned)row & 7u) << 4));
}
__device__ __forceinline__ unsigned pack_bf2(float a, float b) {
    __nv_bfloat16 x = __float2bfloat16(a), y = __float2bfloat16(b);
    return (unsigned)*(unsigned short*)&x | ((unsigned)*(unsigned short*)&y << 16);
}

// ---------------- small kernels ----------------
__global__ void k_zero() {
    int t = threadIdx.x;
    if (t == 0) g_amax_bits = 0u;
    if (t < NEXP) { g_count[t] = 0; g_cursor[t] = 0; }
}

__global__ void k_amax(const float4* __restrict__ x, int n4) {
    float m = 0.f;
    int stride = gridDim.x*blockDim.x;
    int i = blockIdx.x*blockDim.x + threadIdx.x;
    for (; i + 3*stride < n4; i += 4*stride) {
        float4 v0 = x[i], v1 = x[i+stride], v2 = x[i+2*stride], v3 = x[i+3*stride];
        m = fmaxf(m, fmaxf(fmaxf(fabsf(v0.x),fabsf(v0.y)),fmaxf(fabsf(v0.z),fabsf(v0.w))));
        m = fmaxf(m, fmaxf(fmaxf(fabsf(v1.x),fabsf(v1.y)),fmaxf(fabsf(v1.z),fabsf(v1.w))));
        m = fmaxf(m, fmaxf(fmaxf(fabsf(v2.x),fabsf(v2.y)),fmaxf(fabsf(v2.z),fabsf(v2.w))));
        m = fmaxf(m, fmaxf(fmaxf(fabsf(v3.x),fabsf(v3.y)),fmaxf(fabsf(v3.z),fabsf(v3.w))));
    }
    for (; i < n4; i += stride) {
        float4 v = x[i];
        m = fmaxf(m, fmaxf(fmaxf(fabsf(v.x),fabsf(v.y)),fmaxf(fabsf(v.z),fabsf(v.w))));
    }
    for (int o = 16; o; o >>= 1) m = fmaxf(m, __shfl_xor_sync(0xffffffffu, m, o));
    __shared__ float sm[8];
    if ((threadIdx.x & 31) == 0) sm[threadIdx.x >> 5] = m;
    __syncthreads();
    if (threadIdx.x < 8) {
        float v = sm[threadIdx.x];
        for (int o = 4; o; o >>= 1) v = fmaxf(v, __shfl_xor_sync(0xffu, v, o));
        if (threadIdx.x == 0) atomicMax(&g_amax_bits, __float_as_uint(v));
    }
}

__global__ void k_setscale() {
    float amax = __uint_as_float(g_amax_bits);
    float s = fmaxf(amax, 1e-12f) / 448.0f;
    g_scale_x = s;
    g_inv_x = 1.0f / s;
}

__device__ __forceinline__ unsigned q2bf(float a, float b, float inv) {
    __nv_fp8_e4m3 qa(a * inv), qb(b * inv);
    return pack_bf2(float(qa), float(qb));
}

__global__ void k_quant(const float4* __restrict__ x4, int n8) {
    float inv = g_inv_x;
    uint4* dst = (uint4*)g_xq;
    int stride = gridDim.x*blockDim.x;
    for (int i = blockIdx.x*blockDim.x + threadIdx.x; i < n8; i += stride) {
        float4 a = x4[2*i], b = x4[2*i+1];
        uint4 o;
        o.x = q2bf(a.x, a.y, inv);
        o.y = q2bf(a.z, a.w, inv);
        o.z = q2bf(b.x, b.y, inv);
        o.w = q2bf(b.z, b.w, inv);
        dst[i] = o;
    }
}

__global__ void k_route(const float* __restrict__ gating) {
    int t = blockIdx.x*blockDim.x + threadIdx.x;
    if (t >= NTOK) return;
    float g[NEXP];
    #pragma unroll
    for (int e = 0; e < NEXP; e++) g[e] = gating[t*NEXP + e];
    int i0 = 0; float b0 = g[0];
    #pragma unroll
    for (int e = 1; e < NEXP; e++) if (g[e] > b0) { b0 = g[e]; i0 = e; }
    int i1 = -1; float b1 = -INFINITY;
    #pragma unroll
    for (int e = 0; e < NEXP; e++) if (e != i0 && g[e] > b1) { b1 = g[e]; i1 = e; }
    float r  = expf(b1 - b0);
    float w0 = 1.f / (1.f + r);
    float w1 = r  / (1.f + r);
    g_eid[2*t]   = i0; g_cw[2*t]   = w0;
    g_eid[2*t+1] = i1; g_cw[2*t+1] = w1;
    atomicAdd(&g_count[i0], 1);
    atomicAdd(&g_count[i1], 1);
}

__global__ void k_sched() {
    if (threadIdx.x != 0 || blockIdx.x != 0) return;
    int off = 0;
    for (int e = 0; e < NEXP; e++) { g_offset[e] = off; off += g_count[e]; }
    g_offset[NEXP] = off;
    int nt = 0;
    for (int e = 0; e < NEXP; e++)
        for (int r = g_offset[e]; r < g_offset[e+1]; r += 128) {
            g_tile_e[nt] = e; g_tile_r[nt] = r; nt++;
        }
    g_ntiles = nt;
}

__global__ void k_scatter() {
    int t = blockIdx.x*blockDim.x + threadIdx.x;
    if (t >= NTOK) return;
    #pragma unroll
    for (int k = 0; k < 2; k++) {
        int a = 2*t + k;
        int e = g_eid[a];
        int pos = atomicAdd(&g_cursor[e], 1);
        int p = g_offset[e] + pos;
        g_list[p] = a;
        g_pos[a] = p;
    }
}

__global__ void k_cvt(const float4* __restrict__ src, __nv_bfloat16* __restrict__ dstb, int n8) {
    uint4* dst = (uint4*)dstb;
    int stride = gridDim.x*blockDim.x;
    int i = blockIdx.x*blockDim.x + threadIdx.x;
    for (; i + 3*stride < n8; i += 4*stride) {
        #pragma unroll
        for (int u = 0; u < 4; u++) {
            int j = i + u*stride;
            float4 a = src[2*j], b = src[2*j+1];
            uint4 o;
            o.x = pack_bf2(a.x, a.y);
            o.y = pack_bf2(a.z, a.w);
            o.z = pack_bf2(b.x, b.y);
            o.w = pack_bf2(b.z, b.w);
            dst[j] = o;
        }
    }
    for (; i < n8; i += stride) {
        float4 a = src[2*i], b = src[2*i+1];
        uint4 o;
        o.x = pack_bf2(a.x, a.y);
        o.y = pack_bf2(a.z, a.w);
        o.z = pack_bf2(b.x, b.y);
        o.w = pack_bf2(b.z, b.w);
        dst[i] = o;
    }
}

// ================= GEMM1 =================
#define G1_STG  49152
#define G1_BOFF 16384
#define G1_SMEM (3*G1_STG)      // 144 KB
#define G1_PITCH 136            // bf16 units; 272B row pitch: uint4-aligned, conflict-free

__device__ __forceinline__ void g1_fill(unsigned sbase, const int* s_tok, const __nv_bfloat16* wb,
                                        int cg, int kc, int buf, int tid) {
    int k0 = kc * 64;
    unsigned st = sbase + (unsigned)buf * G1_STG;
    #pragma unroll
    for (int i = 0; i < 2; i++) {
        int idx = tid + i*512;
        int r = idx >> 3, c = idx & 7;
        int tok = s_tok[r];
        unsigned dst = st + sw128((unsigned)(r*128 + c*16));
        const void* src = g_xq + ((size_t)(tok < 0 ? 0 : tok) * DMODEL + k0 + c*8);
        cpasync16z(dst, src, tok < 0 ? 0 : 16);
    }
    #pragma unroll
    for (int i = 0; i < 4; i++) {
        int idx = tid + i*512;
        int r = idx >> 3, c = idx & 7;
        int wrow = cg*128 + (r & 127) + ((r >> 7) ? DFF : 0);
        unsigned dst = st + G1_BOFF + sw128((unsigned)(r*128 + c*16));
        cpasync16(dst, wb + (size_t)wrow*DMODEL + k0 + c*8);
    }
}

__global__ __launch_bounds__(512,1) void k_gemm1(const float* __restrict__ w13_scale) {
    int slot = blockIdx.y;
    if (slot >= g_ntiles) return;
    int cg = blockIdx.x;
    int e = g_tile_e[slot], row_base = g_tile_r[slot];
    int rows = min(128, g_offset[e+1] - row_base);

    extern __shared__ char smc[];
    __shared__ int s_tok[128];
    unsigned sbase = smem_u32(smc);
    int tid  = threadIdx.x;
    int wid  = tid >> 5, lane = tid & 31;
    int m0   = (wid & 3) * 32;
    int n0   = (wid >> 2) * 32;
    const __nv_bfloat16* wb = g_w13 + (size_t)e * 2*DFF*DMODEL;

    if (tid < 128) s_tok[tid] = (tid < rows) ? (g_list[row_base + tid] >> 1) : -1;
    __syncthreads();

    g1_fill(sbase, s_tok, wb, cg, 0, 0, tid); CP_COMMIT();
    g1_fill(sbase, s_tok, wb, cg, 1, 1, tid); CP_COMMIT();

    float acc[2][8][4];
    #pragma unroll
    for (int a = 0; a < 2; a++)
        #pragma unroll
        for (int b = 0; b < 8; b++)
            #pragma unroll
            for (int c = 0; c < 4; c++) acc[a][b][c] = 0.f;

    int arow = lane & 15, ahalf = lane >> 4;
    const int NT = DMODEL / 64;
    for (int kt = 0; kt < NT; kt++) {
        if (kt + 2 < NT) { CP_WAIT1(); } else { CP_WAIT0(); }
        __syncthreads();
        if (kt + 2 < NT) { g1_fill(sbase, s_tok, wb, cg, kt+2, (kt+2)%3, tid); CP_COMMIT(); }

        unsigned st = sbase + (unsigned)(kt % 3) * G1_STG;
        #pragma unroll
        for (int kk = 0; kk < 4; kk++) {
            unsigned af[2][4];
            #pragma unroll
            for (int mi = 0; mi < 2; mi++)
                ldsm4(af[mi][0], af[mi][1], af[mi][2], af[mi][3],
                      ldsm_addr(st, m0 + mi*16 + arow, ahalf, kk));
            #pragma unroll
            for (int side = 0; side < 2; side++) {
                #pragma unroll
                for (int nf = 0; nf < 2; nf++) {
                    unsigned b0, b1, b2, b3;
                    int brow = side*128 + n0 + nf*16 + arow;
                    ldsm4(b0, b1, b2, b3, ldsm_addr(st + G1_BOFF, brow, ahalf, kk));
                    #pragma unroll
                    for (int mi = 0; mi < 2; mi++) {
                        mma16816(acc[mi][side*4 + nf*2 + 0], af[mi], b0, b2);
                        mma16816(acc[mi][side*4 + nf*2 + 1], af[mi], b1, b3);
                    }
                }
            }
        }
    }

    // epilogue: silu(gate)*up -> hi/lo bf16 split; stage via smem; coalesced store
    __syncthreads();
    float sc = g_scale_x * __ldg(w13_scale + e);
    __nv_bfloat16* shi = (__nv_bfloat16*)smc;
    __nv_bfloat16* slo = shi + 128*G1_PITCH;
    int qrow = lane >> 2, qc2 = (lane & 3) * 2;
    #pragma unroll
    for (int mi = 0; mi < 2; mi++)
        #pragma unroll
        for (int half = 0; half < 2; half++) {
            int r = m0 + mi*16 + half*8 + qrow;
            int ei = half*2;
            #pragma unroll
            for (int j = 0; j < 4; j++) {
                float g0 = acc[mi][j][ei]     * sc;
                float g1 = acc[mi][j][ei+1]   * sc;
                float u0 = acc[mi][4+j][ei]   * sc;
                float u1 = acc[mi][4+j][ei+1] * sc;
                float h0 = (g0 / (1.f + expf(-g0))) * u0;
                float h1 = (g1 / (1.f + expf(-g1))) * u1;
                __nv_bfloat16 a0 = __float2bfloat16(h0), a1 = __float2bfloat16(h1);
                float l0 = h0 - __bfloat162float(a0);
                float l1 = h1 - __bfloat162float(a1);
                int col = n0 + j*8 + qc2;
                *(unsigned*)(shi + r*G1_PITCH + col) =
                    (unsigned)*(unsigned short*)&a0 | ((unsigned)*(unsigned short*)&a1 << 16);
                *(unsigned*)(slo + r*G1_PITCH + col) = pack_bf2(l0, l1);
            }
        }
    __syncthreads();
    #pragma unroll
    for (int it = 0; it < 4; it++) {
        int i = tid + it*512;
        int r = i >> 4, c = i & 15;
        if (r < rows) {
            size_t off = (size_t)(row_base + r) * DFF + (size_t)cg*128 + c*8;
            *(uint4*)(g_hhi + off) = *(const uint4*)(shi + r*G1_PITCH + c*8);
            *(uint4*)(g_hlo + off) = *(const uint4*)(slo + r*G1_PITCH + c*8);
        }
    }
}

// ================= GEMM2 =================
#define G2_STG   65536
#define G2_ALOFF 16384
#define G2_BOFF  32768
#define G2_SMEM  (3*G2_STG)     // 192 KB
#define G2_PITCH 260            // float units; 1040B pitch: float4-aligned, conflict-free

__device__ __forceinline__ void g2_fill(unsigned sbase, int row_base, const __nv_bfloat16* wb,
                                        int cgo, int kc, int buf, int tid) {
    int k0 = kc * 64;
    unsigned st = sbase + (unsigned)buf * G2_STG;
    #pragma unroll
    for (int i = 0; i < 2; i++) {
        int idx = tid + i*512;
        int r = idx >> 3, c = idx & 7;
        unsigned swo = sw128((unsigned)(r*128 + c*16));
        size_t off = (size_t)(row_base + r) * DFF + k0 + c*8;
        cpasync16(st + swo,            g_hhi + off);
        cpasync16(st + G2_ALOFF + swo, g_hlo + off);
    }
    #pragma unroll
    for (int i = 0; i < 4; i++) {
        int idx = tid + i*512;
        int r = idx >> 3, c = idx & 7;
        int n = cgo*256 + r;
        unsigned dst = st + G2_BOFF + sw128((unsigned)(r*128 + c*16));
        cpasync16(dst, wb + (size_t)n*DFF + k0 + c*8);
    }
}

__global__ __launch_bounds__(512,1) void k_gemm2(const float* __restrict__ w2_scale) {
    int slot = blockIdx.y;
    if (slot >= g_ntiles) return;
    int cgo = blockIdx.x;
    int e = g_tile_e[slot], row_base = g_tile_r[slot];
    int rows = min(128, g_offset[e+1] - row_base);

    extern __shared__ char smc[];
    unsigned sbase = smem_u32(smc);
    int tid  = threadIdx.x;
    int wid  = tid >> 5, lane = tid & 31;
    int m0   = (wid & 3) * 32;
    int n0   = (wid >> 2) * 64;
    const __nv_bfloat16* wb = g_w2 + (size_t)e * DMODEL * DFF;

    g2_fill(sbase, row_base, wb, cgo, 0, 0, tid); CP_COMMIT();
    g2_fill(sbase, row_base, wb, cgo, 1, 1, tid); CP_COMMIT();

    float acc[2][8][4];
    #pragma unroll
    for (int a = 0; a < 2; a++)
        #pragma unroll
        for (int b = 0; b < 8; b++)
            #pragma unroll
            for (int c = 0; c < 4; c++) acc[a][b][c] = 0.f;

    int arow = lane & 15, ahalf = lane >> 4;
    const int NT = DFF / 64;
    for (int kt = 0; kt < NT; kt++) {
        if (kt + 2 < NT) { CP_WAIT1(); } else { CP_WAIT0(); }
        __syncthreads();
        if (kt + 2 < NT) { g2_fill(sbase, row_base, wb, cgo, kt+2, (kt+2)%3, tid); CP_COMMIT(); }

        unsigned st = sbase + (unsigned)(kt % 3) * G2_STG;
        #pragma unroll
        for (int kk = 0; kk < 4; kk++) {
            unsigned ah[2][4], al[2][4];
            #pragma unroll
            for (int mi = 0; mi < 2; mi++) {
                ldsm4(ah[mi][0], ah[mi][1], ah[mi][2], ah[mi][3],
                      ldsm_addr(st,            m0 + mi*16 + arow, ahalf, kk));
                ldsm4(al[mi][0], al[mi][1], al[mi][2], al[mi][3],
                      ldsm_addr(st + G2_ALOFF, m0 + mi*16 + arow, ahalf, kk));
            }
            #pragma unroll
            for (int nf = 0; nf < 4; nf++) {
                unsigned b0, b1, b2, b3;
                int brow = n0 + nf*16 + arow;
                ldsm4(b0, b1, b2, b3, ldsm_addr(st + G2_BOFF, brow, ahalf, kk));
                #pragma unroll
                for (int mi = 0; mi < 2; mi++) {
                    mma16816(acc[mi][nf*2 + 0], ah[mi], b0, b2);
                    mma16816(acc[mi][nf*2 + 0], al[mi], b0, b2);
                    mma16816(acc[mi][nf*2 + 1], ah[mi], b1, b3);
                    mma16816(acc[mi][nf*2 + 1], al[mi], b1, b3);
                }
            }
        }
    }

    // epilogue: stage via smem, coalesced float4 store
    __syncthreads();
    float sc = __ldg(w2_scale + e);
    float* sC = (float*)smc;
    int qrow = lane >> 2, qc2 = (lane & 3) * 2;
    #pragma unroll
    for (int mi = 0; mi < 2; mi++)
        #pragma unroll
        for (int half = 0; half < 2; half++) {
            int r = m0 + mi*16 + half*8 + qrow;
            int ei = half*2;
            #pragma unroll
            for (int j = 0; j < 8; j++) {
                float2 v;
                v.x = acc[mi][j][ei]   * sc;
                v.y = acc[mi][j][ei+1] * sc;
                *(float2*)(sC + r*G2_PITCH + n0 + j*8 + qc2) = v;
            }
        }
    __syncthreads();
    #pragma unroll
    for (int it = 0; it < 16; it++) {
        int i = tid + it*512;
        int r = i >> 6, c = i & 63;
        if (r < rows) {
            *(float4*)(g_part + (size_t)(row_base + r) * DMODEL + (size_t)cgo*256 + c*4) =
                *(const float4*)(sC + r*G2_PITCH + c*4);
        }
    }
}

__global__ void k_combine(float* __restrict__ out) {
    const int n4 = NTOK*DMODEL/4;
    const float4* part4 = (const float4*)g_part;
    int stride = gridDim.x*blockDim.x;
    int i = blockIdx.x*blockDim.x + threadIdx.x;
    for (; i + stride < n4; i += 2*stride) {
        #pragma unroll
        for (int u = 0; u < 2; u++) {
            int j = i + u*stride;
            int t  = j >> 9;
            int c4 = j & 511;
            float w0 = g_cw[2*t], w1 = g_cw[2*t+1];
            int p0 = g_pos[2*t], p1 = g_pos[2*t+1];
            float4 a = part4[(size_t)p0*512 + c4];
            float4 b = part4[(size_t)p1*512 + c4];
            float4 o;
            o.x = w0*a.x + w1*b.x;
            o.y = w0*a.y + w1*b.y;
            o.z = w0*a.z + w1*b.z;
            o.w = w0*a.w + w1*b.w;
            ((float4*)out)[j] = o;
        }
    }
    for (; i < n4; i += stride) {
        int t  = i >> 9;
        int c4 = i & 511;
        float w0 = g_cw[2*t], w1 = g_cw[2*t+1];
        int p0 = g_pos[2*t], p1 = g_pos[2*t+1];
        float4 a = part4[(size_t)p0*512 + c4];
        float4 b = part4[(size_t)p1*512 + c4];
        float4 o;
        o.x = w0*a.x + w1*b.x;
        o.y = w0*a.y + w1*b.y;
        o.z = w0*a.z + w1*b.z;
        o.w = w0*a.w + w1*b.w;
        ((float4*)out)[i] = o;
    }
}

// ---------------- launch ----------------
extern "C" void kernel_launch(void* const* d_in, const int* in_sizes, int n_in,
                              void* d_out, int out_size) {
    const float* x      = (const float*)d_in[0];
    const float* gating = (const float*)d_in[1];
    const float* w13q   = (const float*)d_in[2];
    const float* w13s   = (const float*)d_in[3];
    const float* w2q    = (const float*)d_in[4];
    const float* w2s    = (const float*)d_in[5];
    float* out = (float*)d_out;

    cudaFuncSetAttribute(k_gemm1, cudaFuncAttributeMaxDynamicSharedMemorySize, G1_SMEM);
    cudaFuncSetAttribute(k_gemm2, cudaFuncAttributeMaxDynamicSharedMemorySize, G2_SMEM);

    __nv_bfloat16* w13d; cudaGetSymbolAddress((void**)&w13d, g_w13);
    __nv_bfloat16* w2d;  cudaGetSymbolAddress((void**)&w2d,  g_w2);

    k_zero<<<1, 32>>>();
    k_amax<<<1184, 256>>>((const float4*)x, NTOK*DMODEL/4);
    k_setscale<<<1, 1>>>();
    k_quant<<<1024, 256>>>((const float4*)x, NTOK*DMODEL/8);
    k_route<<<NTOK/256, 256>>>(gating);
    k_sched<<<1, 1>>>();
    k_scatter<<<NTOK/256, 256>>>();
    k_cvt<<<2368, 256>>>((const float4*)w13q, w13d, NEXP*2*DFF*DMODEL/8);
    k_cvt<<<2368, 256>>>((const float4*)w2q,  w2d,  NEXP*DMODEL*DFF/8);

    dim3 gg1(16, MAXTILES);
    k_gemm1<<<gg1, 512, G1_SMEM>>>(w13s);
    dim3 gg2(8, MAXTILES);
    k_gemm2<<<gg2, 512, G2_SMEM>>>(w2s);

    k_combine<<<1184, 256>>>(out);
}